// round 6
// baseline (speedup 1.0000x reference)
#include <cuda_runtime.h>
#include <cstdint>

#define N_TOK 32768
#define DIM 768
#define NE 64
#define NH 256
#define NH2 128
#define NO 2

// ---------------- scratch (no allocations allowed) ----------------
__device__ float g_mu[N_TOK];
__device__ float g_rstd[N_TOK];
__device__ int g_hist[NE];
__device__ int g_off[NE + 1];
__device__ int g_cur[NE];
__device__ int g_tokidx[N_TOK];
__device__ int g_ntiles;
__device__ int g_next;  // persistent-CTA tile stealing counter
__device__ int g_p64;   // 1 if properties buffer is int64, 0 if int32
#define MAXT 320
__device__ int g_tile_head[MAXT];
__device__ int g_tile_start[MAXT];
__device__ int g_tile_rows[MAXT];

// ---------------- helpers ----------------
__device__ __forceinline__ void mma_tf32(float* d, const uint32_t* a, const uint32_t* b) {
    asm volatile(
        "mma.sync.aligned.m16n8k8.row.col.f32.tf32.tf32.f32 "
        "{%0,%1,%2,%3}, {%4,%5,%6,%7}, {%8,%9}, {%0,%1,%2,%3};\n"
        : "+f"(d[0]), "+f"(d[1]), "+f"(d[2]), "+f"(d[3])
        : "r"(a[0]), "r"(a[1]), "r"(a[2]), "r"(a[3]), "r"(b[0]), "r"(b[1]));
}

__device__ __forceinline__ void cp16(uint32_t dst_smem, const void* src) {
    asm volatile("cp.async.cg.shared.global [%0], [%1], 16;\n" ::"r"(dst_smem), "l"(src));
}
#define CP_COMMIT() asm volatile("cp.async.commit_group;\n" ::: "memory")
#define CP_WAIT0() asm volatile("cp.async.wait_group 0;\n" ::: "memory")

__device__ __forceinline__ int get_prop(const void* props, int t, int p64) {
    int v;
    if (p64) v = (int)((const long long*)props)[t];
    else     v = ((const int*)props)[t];
    return v & (NE - 1);
}

// ---------------- kernel 0: reset + dtype detection ----------------
__global__ void k_reset(const unsigned* __restrict__ pw) {
    if (threadIdx.x < NE) g_hist[threadIdx.x] = 0;
    if (threadIdx.x < 32) {
        int odd_nonzero = 0;
#pragma unroll
        for (int i = 0; i < 4; i++)
            if (pw[2 * (threadIdx.x + 32 * i) + 1] != 0u) odd_nonzero = 1;
        unsigned b = __ballot_sync(0xFFFFFFFFu, odd_nonzero);
        if (threadIdx.x == 0) g_p64 = (b == 0u) ? 1 : 0;
    }
}

// ---------------- kernel 1: LN stats + histogram + masked-output zero ----------------
__global__ void k_stats(const float* __restrict__ hidden,
                        const void* __restrict__ props,
                        const float* __restrict__ mask,
                        float* __restrict__ out) {
    int token = blockIdx.x * 8 + (threadIdx.x >> 5);
    int lane = threadIdx.x & 31;
    const float4* xr = (const float4*)(hidden + (size_t)token * DIM);
    float s = 0.f, q = 0.f;
#pragma unroll
    for (int i = 0; i < DIM / 128; i++) {
        float4 v = xr[lane + 32 * i];
        s += v.x + v.y + v.z + v.w;
        q += v.x * v.x + v.y * v.y + v.z * v.z + v.w * v.w;
    }
#pragma unroll
    for (int o = 16; o > 0; o >>= 1) {
        s += __shfl_xor_sync(0xFFFFFFFFu, s, o);
        q += __shfl_xor_sync(0xFFFFFFFFu, q, o);
    }
    if (lane == 0) {
        float mu = s * (1.f / DIM);
        float var = q * (1.f / DIM) - mu * mu;
        g_mu[token] = mu;
        g_rstd[token] = rsqrtf(var + 1e-5f);
        float m = mask[token];
        if (m > 0.f) {
            atomicAdd(&g_hist[get_prop(props, token, g_p64)], 1);
        } else {
            out[token * 2 + 0] = 0.f;
            out[token * 2 + 1] = 0.f;
        }
    }
}

// ---------------- kernel 2: scan + tile plan (single block) ----------------
__global__ void k_plan() {
    if (threadIdx.x == 0) {
        int off = 0, nt = 0;
        for (int e = 0; e < NE; e++) {
            g_off[e] = off;
            int c = g_hist[e];
            for (int s = 0; s < c && nt < MAXT; s += 128) {
                g_tile_head[nt] = e;
                g_tile_start[nt] = off + s;
                g_tile_rows[nt] = min(128, c - s);
                nt++;
            }
            g_cur[e] = 0;
            off += c;
        }
        g_off[NE] = off;
        g_ntiles = nt;
        g_next = 0;
    }
}

// ---------------- kernel 3: scatter (block-local ranks, 1 atomic/head/block) ----
__global__ void k_scatter(const void* __restrict__ props,
                          const float* __restrict__ mask) {
    __shared__ int h[NE], bs[NE];
    int tid = threadIdx.x;
    int t = blockIdx.x * 512 + tid;
    if (tid < NE) h[tid] = 0;
    __syncthreads();
    int p = -1, loc = 0;
    if (mask[t] > 0.f) {
        p = get_prop(props, t, g_p64);
        loc = atomicAdd(&h[p], 1);
    }
    __syncthreads();
    if (tid < NE && h[tid] > 0) bs[tid] = atomicAdd(&g_cur[tid], h[tid]);
    __syncthreads();
    if (p >= 0) {
        int dst = g_off[p] + bs[p] + loc;
        if (dst >= 0 && dst < N_TOK) g_tokidx[dst] = t;
    }
}

// ---------------- kernel 4: fused grouped adapter (persistent CTAs) ----------------
#define LDA 36    // (36 % 32 == 4) -> conflict-free A-frag LDS
#define LDW 264   // (264 % 32 == 8) -> conflict-free B-frag LDS
#define LDW2 136  // (136 % 32 == 8)
#define LDH 260   // (260 % 32 == 4) -> conflict-free GEMM2 A-frag LDS
#define LDH2 132

// floats: A 4608 + W 16896 + H1 33280 + GB 1536 + B1 256 + B2 128 + W3T 256 + TOK 128
#define SMEM_FLOATS (128 * LDA + 2 * 32 * LDW + 128 * LDH + 2 * DIM + 256 + 128 + 256 + 128)
#define SMEM_BYTES (SMEM_FLOATS * 4)

__global__ __launch_bounds__(512) void k_main(
    const float* __restrict__ hidden, const float* __restrict__ base,
    const float* __restrict__ ln_g, const float* __restrict__ ln_b,
    const float* __restrict__ W1, const float* __restrict__ b1,
    const float* __restrict__ W2, const float* __restrict__ b2,
    const float* __restrict__ W3, const float* __restrict__ b3,
    float* __restrict__ out)
{
    extern __shared__ float sm[];
    float* sA = sm;                        // 4608
    float* sW = sA + 128 * LDA;            // 16896
    float* sH1 = sW + 2 * 32 * LDW;        // 33280
    float* sGB = sH1 + 128 * LDH;          // 1536
    float* sB1 = sGB + 2 * DIM;            // 256
    float* sB2 = sB1 + 256;                // 128
    float* sW3T = sB2 + 128;               // 256 ([2][128] transposed)
    int* sTok = (int*)(sW3T + 256);        // 128
    float* sH2 = sH1;                      // reuses H1 region after GEMM2
    __shared__ int s_tile;

    const int tid = threadIdx.x;
    const int wid = tid >> 5;
    const int lane = tid & 31;
    const int g = lane >> 2;
    const int t4 = lane & 3;
    const int arow = tid >> 2;
    const int acol = (tid & 3) * 8;
    const int wm = wid >> 2;
    const int wn = wid & 3;

    const uint32_t* sAu = (const uint32_t*)sA;
    const uint32_t* sH1u = (const uint32_t*)sH1;
    const uint32_t swbase = (uint32_t)__cvta_generic_to_shared(sW);

#define CP_W1(k0, buf)                                                             \
    {                                                                              \
        const float* src0 = W1 + ((size_t)e * DIM + (k0)) * NH;                    \
        _Pragma("unroll") for (int i = 0; i < 4; i++) {                            \
            int idx = tid + 512 * i;                                               \
            int r = idx >> 6, c = (idx & 63) * 4;                                  \
            cp16(swbase + (uint32_t)(((buf)*32 * LDW + r * LDW + c) * 4),          \
                 src0 + r * NH + c);                                               \
        }                                                                          \
        CP_COMMIT();                                                               \
    }
#define CP_W2(k0, buf)                                                              \
    {                                                                               \
        const float* src0 = W2 + ((size_t)e * NH + (k0)) * NH2;                     \
        _Pragma("unroll") for (int i = 0; i < 2; i++) {                             \
            int idx = tid + 512 * i;                                                \
            int r = idx >> 5, c = (idx & 31) * 4;                                   \
            cp16(swbase + (uint32_t)(((buf)*32 * LDW2 + r * LDW2 + c) * 4),         \
                 src0 + r * NH2 + c);                                               \
        }                                                                           \
        CP_COMMIT();                                                                \
    }

    for (;;) {
        if (tid == 0) s_tile = atomicAdd(&g_next, 1);
        __syncthreads();
        const int tile = s_tile;
        if (tile >= g_ntiles) break;

        const int e = g_tile_head[tile] & (NE - 1);
        const int seg = g_tile_start[tile];
        const int rows = g_tile_rows[tile];

        // ---- tile prologue: tokens, gamma/beta, biases, W3^T, W1 chunk0 ----
        // (ranges may overlap in tid — a thread can serve several roles; every
        //  destination is FULLY covered by construction)
        if (tid < 128) {
            int tok = -1;
            if (tid < rows) {
                tok = g_tokidx[seg + tid];
                if (tok < 0 || tok >= N_TOK) tok = -1;
            }
            sTok[tid] = tok;
        }
        if (tid < DIM / 4) {  // 192 threads
            ((float4*)sGB)[tid] = ((const float4*)(ln_g + (size_t)e * DIM))[tid];
            ((float4*)(sGB + DIM))[tid] = ((const float4*)(ln_b + (size_t)e * DIM))[tid];
        }
        if (tid >= 192 && tid < 256)   // 64 threads x float4 = 256 (b1)
            ((float4*)sB1)[tid - 192] = ((const float4*)(b1 + (size_t)e * NH))[tid - 192];
        if (tid >= 256 && tid < 288)   // 32 threads x float4 = 128 (b2)
            ((float4*)sB2)[tid - 256] = ((const float4*)(b2 + (size_t)e * NH2))[tid - 256];
        if (tid >= 288 && tid < 416) { // 128 threads, BOTH output cols each => 256/256
            int k = tid - 288;
            const float* w3e = W3 + (size_t)e * (NH2 * NO);
            sW3T[k] = w3e[k * 2 + 0];
            sW3T[128 + k] = w3e[k * 2 + 1];
        }
        CP_W1(0, 0);
        __syncthreads();

        const int tokr = sTok[arow];
        float mu = 0.f, rs = 0.f;
        const float* xrow = hidden;
        if (tokr >= 0) {
            mu = g_mu[tokr];
            rs = g_rstd[tokr];
            xrow = hidden + (size_t)tokr * DIM;
        }

        // ===================== GEMM1: [128,768] x [768,256] =====================
        float acc1[2][8][4];
#pragma unroll
        for (int i = 0; i < 2; i++)
#pragma unroll
            for (int j = 0; j < 8; j++)
#pragma unroll
                for (int q = 0; q < 4; q++) acc1[i][j][q] = 0.f;

        float4 x0, x1, g0, g1, c0, c1;
        if (tokr >= 0) {
            x0 = *(const float4*)(xrow + acol);
            x1 = *(const float4*)(xrow + acol + 4);
        }
        g0 = *(const float4*)(sGB + acol);
        g1 = *(const float4*)(sGB + acol + 4);
        c0 = *(const float4*)(sGB + DIM + acol);
        c1 = *(const float4*)(sGB + DIM + acol + 4);

        for (int i = 0; i < DIM / 32; i++) {
            const int cur = i & 1;
            const int k0 = i * 32;
            CP_WAIT0();
            __syncthreads();
            if (i < DIM / 32 - 1) CP_W1(k0 + 32, cur ^ 1);
            {
                float* d = &sA[arow * LDA + acol];
                if (tokr >= 0) {
                    float4 o0, o1;
                    o0.x = (x0.x - mu) * rs * g0.x + c0.x;
                    o0.y = (x0.y - mu) * rs * g0.y + c0.y;
                    o0.z = (x0.z - mu) * rs * g0.z + c0.z;
                    o0.w = (x0.w - mu) * rs * g0.w + c0.w;
                    o1.x = (x1.x - mu) * rs * g1.x + c1.x;
                    o1.y = (x1.y - mu) * rs * g1.y + c1.y;
                    o1.z = (x1.z - mu) * rs * g1.z + c1.z;
                    o1.w = (x1.w - mu) * rs * g1.w + c1.w;
                    *(float4*)d = o0;
                    *(float4*)(d + 4) = o1;
                } else {
                    *(float4*)d = make_float4(0.f, 0.f, 0.f, 0.f);
                    *(float4*)(d + 4) = make_float4(0.f, 0.f, 0.f, 0.f);
                }
            }
            if (i < DIM / 32 - 1) {
                int kn = k0 + 32;
                if (tokr >= 0) {
                    x0 = *(const float4*)(xrow + kn + acol);
                    x1 = *(const float4*)(xrow + kn + acol + 4);
                }
                g0 = *(const float4*)(sGB + kn + acol);
                g1 = *(const float4*)(sGB + kn + acol + 4);
                c0 = *(const float4*)(sGB + DIM + kn + acol);
                c1 = *(const float4*)(sGB + DIM + kn + acol + 4);
            }
            __syncthreads();
            const uint32_t* wb = (const uint32_t*)(sW + cur * 32 * LDW);
#pragma unroll
            for (int kk = 0; kk < 32; kk += 8) {
                uint32_t afr[2][4];
#pragma unroll
                for (int m = 0; m < 2; m++) {
                    int r0 = wm * 32 + m * 16;
                    afr[m][0] = sAu[(r0 + g) * LDA + kk + t4];
                    afr[m][1] = sAu[(r0 + g + 8) * LDA + kk + t4];
                    afr[m][2] = sAu[(r0 + g) * LDA + kk + t4 + 4];
                    afr[m][3] = sAu[(r0 + g + 8) * LDA + kk + t4 + 4];
                }
#pragma unroll
                for (int j = 0; j < 8; j++) {
                    uint32_t bfr[2];
                    int c = wn * 64 + j * 8 + g;
                    bfr[0] = wb[(kk + t4) * LDW + c];
                    bfr[1] = wb[(kk + t4 + 4) * LDW + c];
                    mma_tf32(acc1[0][j], afr[0], bfr);
                    mma_tf32(acc1[1][j], afr[1], bfr);
                }
            }
        }
        // GEMM2 chunk-0 prefetch: W2 buf0 region disjoint from W1 buf1 (last read)
        CP_W2(0, 0);
        // store acc1 -> sH1 with fused bias + ReLU
#pragma unroll
        for (int m = 0; m < 2; m++) {
            int r0 = wm * 32 + m * 16 + g;
#pragma unroll
            for (int j = 0; j < 8; j++) {
                int c = wn * 64 + j * 8 + 2 * t4;
                float bx = sB1[c], by = sB1[c + 1];
                *(float2*)&sH1[r0 * LDH + c] =
                    make_float2(fmaxf(acc1[m][j][0] + bx, 0.f), fmaxf(acc1[m][j][1] + by, 0.f));
                *(float2*)&sH1[(r0 + 8) * LDH + c] =
                    make_float2(fmaxf(acc1[m][j][2] + bx, 0.f), fmaxf(acc1[m][j][3] + by, 0.f));
            }
        }

        // ===================== GEMM2: [128,256] x [256,128] =====================
        float acc2[2][4][4];
#pragma unroll
        for (int i = 0; i < 2; i++)
#pragma unroll
            for (int j = 0; j < 4; j++)
#pragma unroll
                for (int q = 0; q < 4; q++) acc2[i][j][q] = 0.f;

        for (int i = 0; i < NH / 32; i++) {
            const int cur = i & 1;
            const int k0 = i * 32;
            CP_WAIT0();
            __syncthreads();  // W2(i) + (i==0) all H1 stores visible
            if (i < NH / 32 - 1) CP_W2(k0 + 32, cur ^ 1);
            const uint32_t* wb = (const uint32_t*)(sW + cur * 32 * LDW2);
#pragma unroll
            for (int kk = 0; kk < 32; kk += 8) {
                uint32_t afr[2][4];
#pragma unroll
                for (int m = 0; m < 2; m++) {
                    int r0 = wm * 32 + m * 16;
                    afr[m][0] = sH1u[(r0 + g) * LDH + k0 + kk + t4];
                    afr[m][1] = sH1u[(r0 + g + 8) * LDH + k0 + kk + t4];
                    afr[m][2] = sH1u[(r0 + g) * LDH + k0 + kk + t4 + 4];
                    afr[m][3] = sH1u[(r0 + g + 8) * LDH + k0 + kk + t4 + 4];
                }
#pragma unroll
                for (int j = 0; j < 4; j++) {
                    uint32_t bfr[2];
                    int c = wn * 32 + j * 8 + g;
                    bfr[0] = wb[(kk + t4) * LDW2 + c];
                    bfr[1] = wb[(kk + t4 + 4) * LDW2 + c];
                    mma_tf32(acc2[0][j], afr[0], bfr);
                    mma_tf32(acc2[1][j], afr[1], bfr);
                }
            }
        }
        __syncthreads();  // all H1 reads done; reuse region as sH2
        // store acc2 -> sH2 with fused bias + ReLU
#pragma unroll
        for (int m = 0; m < 2; m++) {
            int r0 = wm * 32 + m * 16 + g;
#pragma unroll
            for (int j = 0; j < 4; j++) {
                int c = wn * 32 + j * 8 + 2 * t4;
                float bx = sB2[c], by = sB2[c + 1];
                *(float2*)&sH2[r0 * LDH2 + c] =
                    make_float2(fmaxf(acc2[m][j][0] + bx, 0.f), fmaxf(acc2[m][j][1] + by, 0.f));
                *(float2*)&sH2[(r0 + 8) * LDH2 + c] =
                    make_float2(fmaxf(acc2[m][j][2] + bx, 0.f), fmaxf(acc2[m][j][3] + by, 0.f));
            }
        }
        __syncthreads();

        // ===================== GEMM3 + epilogue: [128,128] x [128,2] =====================
        if (tid < 256) {
            int r = tid >> 1, c = tid & 1;
            if (r < rows) {
                int gt = sTok[r];
                if (gt >= 0) {
                    const float4* h4 = (const float4*)&sH2[r * LDH2];
                    const float4* w4 = (const float4*)&sW3T[c * 128];
                    float s = 0.f;
#pragma unroll
                    for (int k = 0; k < 32; k++) {
                        float4 a = h4[k], b = w4[k];
                        s += a.x * b.x + a.y * b.y + a.z * b.z + a.w * b.w;
                    }
                    float o = 0.7f * (s + b3[(size_t)e * NO + c]) +
                              0.3f * base[(size_t)gt * NO + c];
                    out[(size_t)gt * NO + c] = o;
                }
            }
        }
        __syncthreads();  // protect smem reuse before next stolen tile
    }
}

// ---------------- launcher ----------------
extern "C" void kernel_launch(void* const* d_in, const int* in_sizes, int n_in,
                              void* d_out, int out_size) {
    const float* hidden = (const float*)d_in[0];
    const float* base = (const float*)d_in[1];
    const void* props = d_in[2];
    const float* mask = (const float*)d_in[3];
    const float* ln_g = (const float*)d_in[4];
    const float* ln_b = (const float*)d_in[5];
    const float* W1 = (const float*)d_in[6];
    const float* b1 = (const float*)d_in[7];
    const float* W2 = (const float*)d_in[8];
    const float* b2 = (const float*)d_in[9];
    const float* W3 = (const float*)d_in[10];
    const float* b3 = (const float*)d_in[11];
    float* out = (float*)d_out;

    cudaFuncSetAttribute(k_main, cudaFuncAttributeMaxDynamicSharedMemorySize, SMEM_BYTES);

    k_reset<<<1, 64>>>((const unsigned*)props);
    k_stats<<<N_TOK / 8, 256>>>(hidden, props, mask, out);
    k_plan<<<1, 32>>>();
    k_scatter<<<N_TOK / 512, 512>>>(props, mask);
    k_main<<<152, 512, SMEM_BYTES>>>(hidden, base, ln_g, ln_b,
                                     W1, b1, W2, b2, W3, b3, out);
}

// round 7
// speedup vs baseline: 1.0029x; 1.0029x over previous
#include <cuda_runtime.h>
#include <cstdint>

#define N_TOK 32768
#define DIM 768
#define NE 64
#define NH 256
#define NH2 128
#define NO 2

// ---------------- scratch (no allocations allowed) ----------------
__device__ float g_mu[N_TOK];
__device__ float g_rstd[N_TOK];
__device__ int g_hist[NE];
__device__ int g_off[NE + 1];
__device__ int g_cur[NE];
__device__ int g_tokidx[N_TOK];
__device__ int g_ntiles;
__device__ int g_next;  // persistent-CTA tile stealing counter
__device__ int g_p64;   // 1 if properties buffer is int64, 0 if int32
#define MAXT 320
__device__ int g_tile_head[MAXT];
__device__ int g_tile_start[MAXT];
__device__ int g_tile_rows[MAXT];

// ---------------- helpers ----------------
__device__ __forceinline__ void mma_tf32(float* d, const uint32_t* a, const uint32_t* b) {
    asm volatile(
        "mma.sync.aligned.m16n8k8.row.col.f32.tf32.tf32.f32 "
        "{%0,%1,%2,%3}, {%4,%5,%6,%7}, {%8,%9}, {%0,%1,%2,%3};\n"
        : "+f"(d[0]), "+f"(d[1]), "+f"(d[2]), "+f"(d[3])
        : "r"(a[0]), "r"(a[1]), "r"(a[2]), "r"(a[3]), "r"(b[0]), "r"(b[1]));
}

__device__ __forceinline__ void cp16(uint32_t dst_smem, const void* src) {
    asm volatile("cp.async.cg.shared.global [%0], [%1], 16;\n" ::"r"(dst_smem), "l"(src));
}
#define CP_COMMIT() asm volatile("cp.async.commit_group;\n" ::: "memory")
#define CP_WAIT0() asm volatile("cp.async.wait_group 0;\n" ::: "memory")

__device__ __forceinline__ int get_prop(const void* props, int t, int p64) {
    int v;
    if (p64) v = (int)((const long long*)props)[t];
    else     v = ((const int*)props)[t];
    return v & (NE - 1);
}

// ---------------- kernel 0: reset + dtype detection ----------------
__global__ void k_reset(const unsigned* __restrict__ pw) {
    if (threadIdx.x < NE) g_hist[threadIdx.x] = 0;
    if (threadIdx.x < 32) {
        int odd_nonzero = 0;
#pragma unroll
        for (int i = 0; i < 4; i++)
            if (pw[2 * (threadIdx.x + 32 * i) + 1] != 0u) odd_nonzero = 1;
        unsigned b = __ballot_sync(0xFFFFFFFFu, odd_nonzero);
        if (threadIdx.x == 0) g_p64 = (b == 0u) ? 1 : 0;
    }
}

// ---------------- kernel 1: LN stats + histogram + masked-output zero ----------------
__global__ void k_stats(const float* __restrict__ hidden,
                        const void* __restrict__ props,
                        const float* __restrict__ mask,
                        float* __restrict__ out) {
    int token = blockIdx.x * 8 + (threadIdx.x >> 5);
    int lane = threadIdx.x & 31;
    const float4* xr = (const float4*)(hidden + (size_t)token * DIM);
    float s = 0.f, q = 0.f;
#pragma unroll
    for (int i = 0; i < DIM / 128; i++) {
        float4 v = xr[lane + 32 * i];
        s += v.x + v.y + v.z + v.w;
        q += v.x * v.x + v.y * v.y + v.z * v.z + v.w * v.w;
    }
#pragma unroll
    for (int o = 16; o > 0; o >>= 1) {
        s += __shfl_xor_sync(0xFFFFFFFFu, s, o);
        q += __shfl_xor_sync(0xFFFFFFFFu, q, o);
    }
    if (lane == 0) {
        float mu = s * (1.f / DIM);
        float var = q * (1.f / DIM) - mu * mu;
        g_mu[token] = mu;
        g_rstd[token] = rsqrtf(var + 1e-5f);
        float m = mask[token];
        if (m > 0.f) {
            atomicAdd(&g_hist[get_prop(props, token, g_p64)], 1);
        } else {
            out[token * 2 + 0] = 0.f;
            out[token * 2 + 1] = 0.f;
        }
    }
}

// ---------------- kernel 2: scan + tile plan (single block) ----------------
__global__ void k_plan() {
    if (threadIdx.x == 0) {
        int off = 0, nt = 0;
        for (int e = 0; e < NE; e++) {
            g_off[e] = off;
            int c = g_hist[e];
            for (int s = 0; s < c && nt < MAXT; s += 128) {
                g_tile_head[nt] = e;
                g_tile_start[nt] = off + s;
                g_tile_rows[nt] = min(128, c - s);
                nt++;
            }
            g_cur[e] = 0;
            off += c;
        }
        g_off[NE] = off;
        g_ntiles = nt;
        g_next = 0;
    }
}

// ---------------- kernel 3: scatter (block-local ranks, 1 atomic/head/block) ----
__global__ void k_scatter(const void* __restrict__ props,
                          const float* __restrict__ mask) {
    __shared__ int h[NE], bs[NE];
    int tid = threadIdx.x;
    int t = blockIdx.x * 512 + tid;
    if (tid < NE) h[tid] = 0;
    __syncthreads();
    int p = -1, loc = 0;
    if (mask[t] > 0.f) {
        p = get_prop(props, t, g_p64);
        loc = atomicAdd(&h[p], 1);
    }
    __syncthreads();
    if (tid < NE && h[tid] > 0) bs[tid] = atomicAdd(&g_cur[tid], h[tid]);
    __syncthreads();
    if (p >= 0) {
        int dst = g_off[p] + bs[p] + loc;
        if (dst >= 0 && dst < N_TOK) g_tokidx[dst] = t;
    }
}

// ---------------- kernel 4: fused grouped adapter (persistent CTAs) ----------------
#define LDA 36    // (36 % 32 == 4) -> conflict-free A-frag LDS
#define LDW 264   // (264 % 32 == 8) -> conflict-free B-frag LDS
#define LDW2 136  // (136 % 32 == 8)
#define LDH 260   // (260 % 32 == 4) -> conflict-free GEMM2 A-frag LDS
#define LDH2 132

// floats: A 4608 + W 16896 + H1 33280 + GB 1536 + B1 256 + B2 128 + W3T 256 + TOK 128
#define SMEM_FLOATS (128 * LDA + 2 * 32 * LDW + 128 * LDH + 2 * DIM + 256 + 128 + 256 + 128)
#define SMEM_BYTES (SMEM_FLOATS * 4)

__global__ __launch_bounds__(512) void k_main(
    const float* __restrict__ hidden, const float* __restrict__ base,
    const float* __restrict__ ln_g, const float* __restrict__ ln_b,
    const float* __restrict__ W1, const float* __restrict__ b1,
    const float* __restrict__ W2, const float* __restrict__ b2,
    const float* __restrict__ W3, const float* __restrict__ b3,
    float* __restrict__ out)
{
    extern __shared__ float sm[];
    float* sA = sm;                        // 4608 (A buffer 0)
    float* sW = sA + 128 * LDA;            // 16896
    float* sH1 = sW + 2 * 32 * LDW;        // 33280
    float* sGB = sH1 + 128 * LDH;          // 1536
    float* sB1 = sGB + 2 * DIM;            // 256
    float* sB2 = sB1 + 256;                // 128
    float* sW3T = sB2 + 128;               // 256 ([2][128] transposed)
    int* sTok = (int*)(sW3T + 256);        // 128
    float* sH2 = sH1;                      // reuses H1 region after GEMM2
    // A buffer 1 aliases the TAIL of the H1 region (H1 is dead during the
    // GEMM1 mainloop; a __syncthreads separates last A-read from H1 stores).
    float* sA1 = sH1 + (128 * LDH - 128 * LDA);  // last 4608 floats of H1
    __shared__ int s_tile;

    const int tid = threadIdx.x;
    const int wid = tid >> 5;
    const int lane = tid & 31;
    const int g = lane >> 2;
    const int t4 = lane & 3;
    const int arow = tid >> 2;
    const int acol = (tid & 3) * 8;
    const int wm = wid >> 2;
    const int wn = wid & 3;

    const uint32_t* sH1u = (const uint32_t*)sH1;
    const uint32_t swbase = (uint32_t)__cvta_generic_to_shared(sW);

#define CP_W1(k0, buf)                                                             \
    {                                                                              \
        const float* src0 = W1 + ((size_t)e * DIM + (k0)) * NH;                    \
        _Pragma("unroll") for (int i = 0; i < 4; i++) {                            \
            int idx = tid + 512 * i;                                               \
            int r = idx >> 6, c = (idx & 63) * 4;                                  \
            cp16(swbase + (uint32_t)(((buf)*32 * LDW + r * LDW + c) * 4),          \
                 src0 + r * NH + c);                                               \
        }                                                                          \
        CP_COMMIT();                                                               \
    }
#define CP_W2(k0, buf)                                                              \
    {                                                                               \
        const float* src0 = W2 + ((size_t)e * NH + (k0)) * NH2;                     \
        _Pragma("unroll") for (int i = 0; i < 2; i++) {                             \
            int idx = tid + 512 * i;                                                \
            int r = idx >> 5, c = (idx & 31) * 4;                                   \
            cp16(swbase + (uint32_t)(((buf)*32 * LDW2 + r * LDW2 + c) * 4),         \
                 src0 + r * NH2 + c);                                               \
        }                                                                           \
        CP_COMMIT();                                                                \
    }

    for (;;) {
        if (tid == 0) s_tile = atomicAdd(&g_next, 1);
        __syncthreads();
        const int tile = s_tile;
        if (tile >= g_ntiles) break;

        const int e = g_tile_head[tile] & (NE - 1);
        const int seg = g_tile_start[tile];
        const int rows = g_tile_rows[tile];
        const bool do_m = (wm * 32) < rows;  // warp m-slice has real rows

        // ---- tile prologue: tokens, gamma/beta, biases, W3^T, W1 chunk0 ----
        if (tid < 128) {
            int tok = -1;
            if (tid < rows) {
                tok = g_tokidx[seg + tid];
                if (tok < 0 || tok >= N_TOK) tok = -1;
            }
            sTok[tid] = tok;
        }
        if (tid < DIM / 4) {  // 192 threads
            ((float4*)sGB)[tid] = ((const float4*)(ln_g + (size_t)e * DIM))[tid];
            ((float4*)(sGB + DIM))[tid] = ((const float4*)(ln_b + (size_t)e * DIM))[tid];
        }
        if (tid >= 192 && tid < 256)   // b1
            ((float4*)sB1)[tid - 192] = ((const float4*)(b1 + (size_t)e * NH))[tid - 192];
        if (tid >= 256 && tid < 288)   // b2
            ((float4*)sB2)[tid - 256] = ((const float4*)(b2 + (size_t)e * NH2))[tid - 256];
        if (tid >= 288 && tid < 416) { // W3^T, both cols per thread => 256/256 covered
            int k = tid - 288;
            const float* w3e = W3 + (size_t)e * (NH2 * NO);
            sW3T[k] = w3e[k * 2 + 0];
            sW3T[128 + k] = w3e[k * 2 + 1];
        }
        CP_W1(0, 0);
        __syncthreads();

        const int tokr = sTok[arow];
        float mu = 0.f, rs = 0.f;
        const float* xrow = hidden;
        if (tokr >= 0) {
            mu = g_mu[tokr];
            rs = g_rstd[tokr];
            xrow = hidden + (size_t)tokr * DIM;
        }

        // ===================== GEMM1: [128,768] x [768,256] =====================
        float acc1[2][8][4];
#pragma unroll
        for (int i = 0; i < 2; i++)
#pragma unroll
            for (int j = 0; j < 8; j++)
#pragma unroll
                for (int q = 0; q < 4; q++) acc1[i][j][q] = 0.f;

        float4 x0, x1, g0, g1, c0, c1;
        if (tokr >= 0) {
            x0 = *(const float4*)(xrow + acol);
            x1 = *(const float4*)(xrow + acol + 4);
        }
        g0 = *(const float4*)(sGB + acol);
        g1 = *(const float4*)(sGB + acol + 4);
        c0 = *(const float4*)(sGB + DIM + acol);
        c1 = *(const float4*)(sGB + DIM + acol + 4);

        // pre-loop: A(0) -> buf0 (visible after first in-loop sync)
        {
            float* d = &sA[arow * LDA + acol];
            if (tokr >= 0) {
                float4 o0, o1;
                o0.x = (x0.x - mu) * rs * g0.x + c0.x;
                o0.y = (x0.y - mu) * rs * g0.y + c0.y;
                o0.z = (x0.z - mu) * rs * g0.z + c0.z;
                o0.w = (x0.w - mu) * rs * g0.w + c0.w;
                o1.x = (x1.x - mu) * rs * g1.x + c1.x;
                o1.y = (x1.y - mu) * rs * g1.y + c1.y;
                o1.z = (x1.z - mu) * rs * g1.z + c1.z;
                o1.w = (x1.w - mu) * rs * g1.w + c1.w;
                *(float4*)d = o0;
                *(float4*)(d + 4) = o1;
            } else {
                *(float4*)d = make_float4(0.f, 0.f, 0.f, 0.f);
                *(float4*)(d + 4) = make_float4(0.f, 0.f, 0.f, 0.f);
            }
        }

        for (int i = 0; i < DIM / 32; i++) {
            const int cur = i & 1;
            const int k0 = i * 32;
            // prefetch regs for chunk i+1 (overlaps CP wait + sync)
            if (i < DIM / 32 - 1) {
                int kn = k0 + 32;
                if (tokr >= 0) {
                    x0 = *(const float4*)(xrow + kn + acol);
                    x1 = *(const float4*)(xrow + kn + acol + 4);
                }
                g0 = *(const float4*)(sGB + kn + acol);
                g1 = *(const float4*)(sGB + kn + acol + 4);
                c0 = *(const float4*)(sGB + DIM + kn + acol);
                c1 = *(const float4*)(sGB + DIM + kn + acol + 4);
            }
            CP_WAIT0();
            __syncthreads();  // W(i) + A(i) visible; MMA(i-1) reads complete
            if (i < DIM / 32 - 1) {
                CP_W1(k0 + 32, cur ^ 1);
                // A(i+1) -> other buffer (overlaps MMA(i) below)
                float* abn = (cur ^ 1) ? sA1 : sA;
                float* d = &abn[arow * LDA + acol];
                if (tokr >= 0) {
                    float4 o0, o1;
                    o0.x = (x0.x - mu) * rs * g0.x + c0.x;
                    o0.y = (x0.y - mu) * rs * g0.y + c0.y;
                    o0.z = (x0.z - mu) * rs * g0.z + c0.z;
                    o0.w = (x0.w - mu) * rs * g0.w + c0.w;
                    o1.x = (x1.x - mu) * rs * g1.x + c1.x;
                    o1.y = (x1.y - mu) * rs * g1.y + c1.y;
                    o1.z = (x1.z - mu) * rs * g1.z + c1.z;
                    o1.w = (x1.w - mu) * rs * g1.w + c1.w;
                    *(float4*)d = o0;
                    *(float4*)(d + 4) = o1;
                } else if (i == 0) {  // padding rows: zero each buffer once
                    *(float4*)d = make_float4(0.f, 0.f, 0.f, 0.f);
                    *(float4*)(d + 4) = make_float4(0.f, 0.f, 0.f, 0.f);
                }
            }
            if (do_m) {
                const uint32_t* ab = (const uint32_t*)(cur ? sA1 : sA);
                const uint32_t* wb = (const uint32_t*)(sW + cur * 32 * LDW);
#pragma unroll
                for (int kk = 0; kk < 32; kk += 8) {
                    uint32_t afr[2][4];
#pragma unroll
                    for (int m = 0; m < 2; m++) {
                        int r0 = wm * 32 + m * 16;
                        afr[m][0] = ab[(r0 + g) * LDA + kk + t4];
                        afr[m][1] = ab[(r0 + g + 8) * LDA + kk + t4];
                        afr[m][2] = ab[(r0 + g) * LDA + kk + t4 + 4];
                        afr[m][3] = ab[(r0 + g + 8) * LDA + kk + t4 + 4];
                    }
#pragma unroll
                    for (int j = 0; j < 8; j++) {
                        uint32_t bfr[2];
                        int c = wn * 64 + j * 8 + g;
                        bfr[0] = wb[(kk + t4) * LDW + c];
                        bfr[1] = wb[(kk + t4 + 4) * LDW + c];
                        mma_tf32(acc1[0][j], afr[0], bfr);
                        mma_tf32(acc1[1][j], afr[1], bfr);
                    }
                }
            }
        }
        // GEMM2 chunk-0 prefetch (W buf0's last GEMM1 read was chunk 22,
        // complete before the final in-loop sync)
        CP_W2(0, 0);
        __syncthreads();  // last MMA's A-reads done before H1 stores (sA1 aliases H1 tail)
        // store acc1 -> sH1 with fused bias + ReLU
        if (do_m) {
#pragma unroll
            for (int m = 0; m < 2; m++) {
                int r0 = wm * 32 + m * 16 + g;
#pragma unroll
                for (int j = 0; j < 8; j++) {
                    int c = wn * 64 + j * 8 + 2 * t4;
                    float bx = sB1[c], by = sB1[c + 1];
                    *(float2*)&sH1[r0 * LDH + c] =
                        make_float2(fmaxf(acc1[m][j][0] + bx, 0.f), fmaxf(acc1[m][j][1] + by, 0.f));
                    *(float2*)&sH1[(r0 + 8) * LDH + c] =
                        make_float2(fmaxf(acc1[m][j][2] + bx, 0.f), fmaxf(acc1[m][j][3] + by, 0.f));
                }
            }
        }

        // ===================== GEMM2: [128,256] x [256,128] =====================
        float acc2[2][4][4];
#pragma unroll
        for (int i = 0; i < 2; i++)
#pragma unroll
            for (int j = 0; j < 4; j++)
#pragma unroll
                for (int q = 0; q < 4; q++) acc2[i][j][q] = 0.f;

        for (int i = 0; i < NH / 32; i++) {
            const int cur = i & 1;
            const int k0 = i * 32;
            CP_WAIT0();
            __syncthreads();  // W2(i) + (i==0) all H1 stores visible
            if (i < NH / 32 - 1) CP_W2(k0 + 32, cur ^ 1);
            if (do_m) {
                const uint32_t* wb = (const uint32_t*)(sW + cur * 32 * LDW2);
#pragma unroll
                for (int kk = 0; kk < 32; kk += 8) {
                    uint32_t afr[2][4];
#pragma unroll
                    for (int m = 0; m < 2; m++) {
                        int r0 = wm * 32 + m * 16;
                        afr[m][0] = sH1u[(r0 + g) * LDH + k0 + kk + t4];
                        afr[m][1] = sH1u[(r0 + g + 8) * LDH + k0 + kk + t4];
                        afr[m][2] = sH1u[(r0 + g) * LDH + k0 + kk + t4 + 4];
                        afr[m][3] = sH1u[(r0 + g + 8) * LDH + k0 + kk + t4 + 4];
                    }
#pragma unroll
                    for (int j = 0; j < 4; j++) {
                        uint32_t bfr[2];
                        int c = wn * 32 + j * 8 + g;
                        bfr[0] = wb[(kk + t4) * LDW2 + c];
                        bfr[1] = wb[(kk + t4 + 4) * LDW2 + c];
                        mma_tf32(acc2[0][j], afr[0], bfr);
                        mma_tf32(acc2[1][j], afr[1], bfr);
                    }
                }
            }
        }
        __syncthreads();  // all H1 reads done; reuse region as sH2
        // store acc2 -> sH2 with fused bias + ReLU
        if (do_m) {
#pragma unroll
            for (int m = 0; m < 2; m++) {
                int r0 = wm * 32 + m * 16 + g;
#pragma unroll
                for (int j = 0; j < 4; j++) {
                    int c = wn * 32 + j * 8 + 2 * t4;
                    float bx = sB2[c], by = sB2[c + 1];
                    *(float2*)&sH2[r0 * LDH2 + c] =
                        make_float2(fmaxf(acc2[m][j][0] + bx, 0.f), fmaxf(acc2[m][j][1] + by, 0.f));
                    *(float2*)&sH2[(r0 + 8) * LDH2 + c] =
                        make_float2(fmaxf(acc2[m][j][2] + bx, 0.f), fmaxf(acc2[m][j][3] + by, 0.f));
                }
            }
        }
        __syncthreads();

        // ===================== GEMM3 + epilogue: [128,128] x [128,2] =====================
        if (tid < 256) {
            int r = tid >> 1, c = tid & 1;
            if (r < rows) {
                int gt = sTok[r];
                if (gt >= 0) {
                    const float4* h4 = (const float4*)&sH2[r * LDH2];
                    const float4* w4 = (const float4*)&sW3T[c * 128];
                    float s = 0.f;
#pragma unroll
                    for (int k = 0; k < 32; k++) {
                        float4 a = h4[k], b = w4[k];
                        s += a.x * b.x + a.y * b.y + a.z * b.z + a.w * b.w;
                    }
                    float o = 0.7f * (s + b3[(size_t)e * NO + c]) +
                              0.3f * base[(size_t)gt * NO + c];
                    out[(size_t)gt * NO + c] = o;
                }
            }
        }
        __syncthreads();  // protect smem reuse before next stolen tile
    }
}

// ---------------- launcher ----------------
extern "C" void kernel_launch(void* const* d_in, const int* in_sizes, int n_in,
                              void* d_out, int out_size) {
    const float* hidden = (const float*)d_in[0];
    const float* base = (const float*)d_in[1];
    const void* props = d_in[2];
    const float* mask = (const float*)d_in[3];
    const float* ln_g = (const float*)d_in[4];
    const float* ln_b = (const float*)d_in[5];
    const float* W1 = (const float*)d_in[6];
    const float* b1 = (const float*)d_in[7];
    const float* W2 = (const float*)d_in[8];
    const float* b2 = (const float*)d_in[9];
    const float* W3 = (const float*)d_in[10];
    const float* b3 = (const float*)d_in[11];
    float* out = (float*)d_out;

    cudaFuncSetAttribute(k_main, cudaFuncAttributeMaxDynamicSharedMemorySize, SMEM_BYTES);

    k_reset<<<1, 64>>>((const unsigned*)props);
    k_stats<<<N_TOK / 8, 256>>>(hidden, props, mask, out);
    k_plan<<<1, 32>>>();
    k_scatter<<<N_TOK / 512, 512>>>(props, mask);
    k_main<<<152, 512, SMEM_BYTES>>>(hidden, base, ln_g, ln_b,
                                     W1, b1, W2, b2, W3, b3, out);
}

// round 9
// speedup vs baseline: 1.1516x; 1.1482x over previous
#include <cuda_runtime.h>
#include <cuda_fp16.h>
#include <cstdint>

#define N_TOK 32768
#define DIM 768
#define NE 64
#define NH 256
#define NH2 128
#define NO 2

// ---------------- scratch (no allocations allowed) ----------------
__device__ float g_mu[N_TOK];
__device__ float g_rstd[N_TOK];
__device__ int g_hist[NE];
__device__ int g_off[NE + 1];
__device__ int g_cur[NE];
__device__ int g_tokidx[N_TOK];
__device__ int g_ntiles;
__device__ int g_next;
__device__ int g_p64;
#define MAXT 320
__device__ int g_tile_head[MAXT];
__device__ int g_tile_start[MAXT];
__device__ int g_tile_rows[MAXT];
// fp16 transposed weights: W1h[e][n][k], W2h[e][n][k]
__device__ __half g_W1h[(size_t)NE * NH * DIM];
__device__ __half g_W2h[(size_t)NE * NH2 * NH];

// ---------------- helpers ----------------
__device__ __forceinline__ void mma_f16(float* d, const uint32_t* a, const uint32_t* b) {
    asm volatile(
        "mma.sync.aligned.m16n8k16.row.col.f32.f16.f16.f32 "
        "{%0,%1,%2,%3}, {%4,%5,%6,%7}, {%8,%9}, {%0,%1,%2,%3};\n"
        : "+f"(d[0]), "+f"(d[1]), "+f"(d[2]), "+f"(d[3])
        : "r"(a[0]), "r"(a[1]), "r"(a[2]), "r"(a[3]), "r"(b[0]), "r"(b[1]));
}

__device__ __forceinline__ void cp16(uint32_t dst_smem, const void* src) {
    asm volatile("cp.async.cg.shared.global [%0], [%1], 16;\n" ::"r"(dst_smem), "l"(src));
}
#define CP_COMMIT() asm volatile("cp.async.commit_group;\n" ::: "memory")
#define CP_WAIT0() asm volatile("cp.async.wait_group 0;\n" ::: "memory")

__device__ __forceinline__ int get_prop(const void* props, int t, int p64) {
    int v;
    if (p64) v = (int)((const long long*)props)[t];
    else     v = ((const int*)props)[t];
    return v & (NE - 1);
}

__device__ __forceinline__ uint32_t h2u(__half2 h) {
    uint32_t u;
    *(__half2*)&u = h;
    return u;
}

// ---------------- kernel 0: reset + dtype detection ----------------
__global__ void k_reset(const unsigned* __restrict__ pw) {
    if (threadIdx.x < NE) g_hist[threadIdx.x] = 0;
    if (threadIdx.x < 32) {
        int odd_nonzero = 0;
#pragma unroll
        for (int i = 0; i < 4; i++)
            if (pw[2 * (threadIdx.x + 32 * i) + 1] != 0u) odd_nonzero = 1;
        unsigned b = __ballot_sync(0xFFFFFFFFu, odd_nonzero);
        if (threadIdx.x == 0) g_p64 = (b == 0u) ? 1 : 0;
    }
}

// ---------------- convert+transpose: W [e][k][n] f32 -> Wh [e][n][k] half ----------------
__global__ void k_cvt1(const float* __restrict__ W1) {
    __shared__ float s[32][33];
    int k0 = blockIdx.x * 32, n0 = blockIdx.y * 32, e = blockIdx.z;
    const float* src = W1 + (size_t)e * DIM * NH;
#pragma unroll
    for (int d = 0; d < 4; d++)
        s[threadIdx.y + 8 * d][threadIdx.x] =
            src[(size_t)(k0 + threadIdx.y + 8 * d) * NH + n0 + threadIdx.x];
    __syncthreads();
    if (threadIdx.x < 16) {
#pragma unroll
        for (int d = 0; d < 4; d++) {
            int n = n0 + threadIdx.y + 8 * d;
            __half2 h = __floats2half2_rn(s[2 * threadIdx.x][threadIdx.y + 8 * d],
                                          s[2 * threadIdx.x + 1][threadIdx.y + 8 * d]);
            ((__half2*)(g_W1h + (size_t)e * NH * DIM + (size_t)n * DIM + k0))[threadIdx.x] = h;
        }
    }
}

__global__ void k_cvt2(const float* __restrict__ W2) {
    __shared__ float s[32][33];
    int k0 = blockIdx.x * 32, n0 = blockIdx.y * 32, e = blockIdx.z;
    const float* src = W2 + (size_t)e * NH * NH2;
#pragma unroll
    for (int d = 0; d < 4; d++)
        s[threadIdx.y + 8 * d][threadIdx.x] =
            src[(size_t)(k0 + threadIdx.y + 8 * d) * NH2 + n0 + threadIdx.x];
    __syncthreads();
    if (threadIdx.x < 16) {
#pragma unroll
        for (int d = 0; d < 4; d++) {
            int n = n0 + threadIdx.y + 8 * d;
            __half2 h = __floats2half2_rn(s[2 * threadIdx.x][threadIdx.y + 8 * d],
                                          s[2 * threadIdx.x + 1][threadIdx.y + 8 * d]);
            ((__half2*)(g_W2h + (size_t)e * NH2 * NH + (size_t)n * NH + k0))[threadIdx.x] = h;
        }
    }
}

// ---------------- kernel 1: LN stats + histogram + masked-output zero ----------------
__global__ void k_stats(const float* __restrict__ hidden,
                        const void* __restrict__ props,
                        const float* __restrict__ mask,
                        float* __restrict__ out) {
    int token = blockIdx.x * 8 + (threadIdx.x >> 5);
    int lane = threadIdx.x & 31;
    const float4* xr = (const float4*)(hidden + (size_t)token * DIM);
    float s = 0.f, q = 0.f;
#pragma unroll
    for (int i = 0; i < DIM / 128; i++) {
        float4 v = xr[lane + 32 * i];
        s += v.x + v.y + v.z + v.w;
        q += v.x * v.x + v.y * v.y + v.z * v.z + v.w * v.w;
    }
#pragma unroll
    for (int o = 16; o > 0; o >>= 1) {
        s += __shfl_xor_sync(0xFFFFFFFFu, s, o);
        q += __shfl_xor_sync(0xFFFFFFFFu, q, o);
    }
    if (lane == 0) {
        float mu = s * (1.f / DIM);
        float var = q * (1.f / DIM) - mu * mu;
        g_mu[token] = mu;
        g_rstd[token] = rsqrtf(var + 1e-5f);
        float m = mask[token];
        if (m > 0.f) {
            atomicAdd(&g_hist[get_prop(props, token, g_p64)], 1);
        } else {
            out[token * 2 + 0] = 0.f;
            out[token * 2 + 1] = 0.f;
        }
    }
}

// ---------------- kernel 2: scan + tile plan ----------------
__global__ void k_plan() {
    if (threadIdx.x == 0) {
        int off = 0, nt = 0;
        for (int e = 0; e < NE; e++) {
            g_off[e] = off;
            int c = g_hist[e];
            for (int s = 0; s < c && nt < MAXT; s += 128) {
                g_tile_head[nt] = e;
                g_tile_start[nt] = off + s;
                g_tile_rows[nt] = min(128, c - s);
                nt++;
            }
            g_cur[e] = 0;
            off += c;
        }
        g_off[NE] = off;
        g_ntiles = nt;
        g_next = 0;
    }
}

// ---------------- kernel 3: scatter ----------------
__global__ void k_scatter(const void* __restrict__ props,
                          const float* __restrict__ mask) {
    __shared__ int h[NE], bs[NE];
    int tid = threadIdx.x;
    int t = blockIdx.x * 512 + tid;
    if (tid < NE) h[tid] = 0;
    __syncthreads();
    int p = -1, loc = 0;
    if (mask[t] > 0.f) {
        p = get_prop(props, t, g_p64);
        loc = atomicAdd(&h[p], 1);
    }
    __syncthreads();
    if (tid < NE && h[tid] > 0) bs[tid] = atomicAdd(&g_cur[tid], h[tid]);
    __syncthreads();
    if (p >= 0) {
        int dst = g_off[p] + bs[p] + loc;
        if (dst >= 0 && dst < N_TOK) g_tokidx[dst] = t;
    }
}

// ---------------- kernel 4: fp16 mma.sync grouped adapter (persistent CTAs) ----------------
// half-word (uint32) row strides:
#define LDAW 20    // A tile [128 rows][16 h2 words + pad4]  (bank = 20g+t4 unique)
#define LDWW 20    // W tile [n rows][16 words + pad4]
#define LDH1W 132  // H1 [128][128 words + pad4] (bank = 4g+t4 unique)
#define LDH2F 132  // H2 f32 [128][128 + pad4]

// smem byte offsets
#define OFF_A0 0u          // 10240
#define OFF_A1 10240u      // 10240
#define OFF_W 20480u       // 2 x 20480
#define OFF_H1 61440u      // 128*132*4 = 67584 (GEMM2 input, half words)
#define OFF_H2 61440u      // f32 [128][132], aliases H1 after GEMM2
#define OFF_GB 129024u     // gamma 3072 + beta 3072
#define OFF_B1 135168u     // 1024
#define OFF_B2 136192u     // 512
#define OFF_W3T 136704u    // 1024
#define OFF_TOK 137728u    // 512
#define SMEM_BYTES 138240u

__global__ __launch_bounds__(512) void k_main(
    const float* __restrict__ hidden, const float* __restrict__ base,
    const float* __restrict__ ln_g, const float* __restrict__ ln_b,
    const float* __restrict__ b1, const float* __restrict__ b2,
    const float* __restrict__ W3, const float* __restrict__ b3,
    float* __restrict__ out)
{
    extern __shared__ char smem[];
    const uint32_t sb = (uint32_t)__cvta_generic_to_shared(smem);
    float* sGB = (float*)(smem + OFF_GB);
    float* sB1 = (float*)(smem + OFF_B1);
    float* sB2 = (float*)(smem + OFF_B2);
    float* sW3T = (float*)(smem + OFF_W3T);
    int* sTok = (int*)(smem + OFF_TOK);
    uint32_t* sH1w = (uint32_t*)(smem + OFF_H1);
    float* sH2 = (float*)(smem + OFF_H2);
    __shared__ int s_tile;

    const int tid = threadIdx.x;
    const int wid = tid >> 5;
    const int lane = tid & 31;
    const int g = lane >> 2;
    const int t4 = lane & 3;
    const int arow = tid >> 2;
    const int wm = wid >> 2;
    const int wn = wid & 3;
    const int acol = (tid & 3) * 8;

    // X store destination (uint4 = 8 halves), tile-invariant
    uint4* xdst0 = (uint4*)(smem + OFF_A0 + (uint32_t)(arow * 80 + (tid & 3) * 16));
    uint4* xdst1 = (uint4*)(smem + OFF_A1 + (uint32_t)(arow * 80 + (tid & 3) * 16));

#define CP_WT1(k0, buf)                                                       \
    {                                                                         \
        const __half* src0 = g_W1h + (size_t)e * NH * DIM + (k0);             \
        _Pragma("unroll") for (int ii = 0; ii < 2; ii++) {                    \
            int idx = tid + 512 * ii; /* < 1024 */                            \
            int n = idx >> 2, kc = idx & 3;                                   \
            cp16(sb + OFF_W + (buf)*20480u + (uint32_t)(n * 80 + kc * 16),    \
                 src0 + (size_t)n * DIM + kc * 8);                            \
        }                                                                     \
        CP_COMMIT();                                                          \
    }
#define CP_WT2(k0, buf)                                                       \
    {                                                                         \
        const __half* src0 = g_W2h + (size_t)e * NH2 * NH + (k0);             \
        {                                                                     \
            int n = tid >> 2, kc = tid & 3; /* 512 cps */                     \
            cp16(sb + OFF_W + (buf)*20480u + (uint32_t)(n * 80 + kc * 16),    \
                 src0 + (size_t)n * NH + kc * 8);                             \
        }                                                                     \
        CP_COMMIT();                                                          \
    }

#define XSTORE(dst, px0, px1, pg0, pg1, pc0, pc1)                                           \
    {                                                                                       \
        uint4 u;                                                                            \
        u.x = h2u(__floats2half2_rn((px0.x - mu) * rs * pg0.x + pc0.x,                      \
                                    (px0.y - mu) * rs * pg0.y + pc0.y));                    \
        u.y = h2u(__floats2half2_rn((px0.z - mu) * rs * pg0.z + pc0.z,                      \
                                    (px0.w - mu) * rs * pg0.w + pc0.w));                    \
        u.z = h2u(__floats2half2_rn((px1.x - mu) * rs * pg1.x + pc1.x,                      \
                                    (px1.y - mu) * rs * pg1.y + pc1.y));                    \
        u.w = h2u(__floats2half2_rn((px1.z - mu) * rs * pg1.z + pc1.z,                      \
                                    (px1.w - mu) * rs * pg1.w + pc1.w));                    \
        *(dst) = u;                                                                         \
    }

    for (;;) {
        if (tid == 0) s_tile = atomicAdd(&g_next, 1);
        __syncthreads();
        const int tile = s_tile;
        if (tile >= g_ntiles) break;

        const int e = g_tile_head[tile] & (NE - 1);
        const int seg = g_tile_start[tile];
        const int rows = g_tile_rows[tile];
        const bool do_m = (wm * 32) < rows;

        // ---- prologue ----
        if (tid < 128) {
            int tok = -1;
            if (tid < rows) {
                tok = g_tokidx[seg + tid];
                if (tok < 0 || tok >= N_TOK) tok = -1;
            }
            sTok[tid] = tok;
        }
        if (tid < DIM / 4) {
            ((float4*)sGB)[tid] = ((const float4*)(ln_g + (size_t)e * DIM))[tid];
            ((float4*)(sGB + DIM))[tid] = ((const float4*)(ln_b + (size_t)e * DIM))[tid];
        }
        if (tid >= 192 && tid < 256)
            ((float4*)sB1)[tid - 192] = ((const float4*)(b1 + (size_t)e * NH))[tid - 192];
        if (tid >= 256 && tid < 288)
            ((float4*)sB2)[tid - 256] = ((const float4*)(b2 + (size_t)e * NH2))[tid - 256];
        if (tid >= 288 && tid < 416) {
            int k = tid - 288;
            const float* w3e = W3 + (size_t)e * (NH2 * NO);
            sW3T[k] = w3e[k * 2 + 0];
            sW3T[128 + k] = w3e[k * 2 + 1];
        }
        CP_WT1(0, 0);
        __syncthreads();

        const int tokr = sTok[arow];
        float mu = 0.f, rs = 0.f;
        const float* xrow = hidden;
        if (tokr >= 0) {
            mu = g_mu[tokr];
            rs = g_rstd[tokr];
            xrow = hidden + (size_t)tokr * DIM;
        }

        // ===================== GEMM1: [128,768] x [768,256], fp16 =====================
        float acc1[2][8][4];
#pragma unroll
        for (int i = 0; i < 2; i++)
#pragma unroll
            for (int j = 0; j < 8; j++)
#pragma unroll
                for (int q = 0; q < 4; q++) acc1[i][j][q] = 0.f;

        // X(0) -> A0
        {
            float4 g0 = *(const float4*)(sGB + acol);
            float4 g1 = *(const float4*)(sGB + acol + 4);
            float4 c0 = *(const float4*)(sGB + DIM + acol);
            float4 c1 = *(const float4*)(sGB + DIM + acol + 4);
            if (tokr >= 0) {
                float4 x0 = *(const float4*)(xrow + acol);
                float4 x1 = *(const float4*)(xrow + acol + 4);
                XSTORE(xdst0, x0, x1, g0, g1, c0, c1);
            } else {
                *xdst0 = make_uint4(0u, 0u, 0u, 0u);
            }
        }

        const uint32_t* aw0 = (const uint32_t*)(smem + OFF_A0);
        const uint32_t* aw1 = (const uint32_t*)(smem + OFF_A1);

        for (int i = 0; i < DIM / 32; i++) {
            const int cur = i & 1;
            const int k0 = i * 32;
            float4 x0, x1, g0, g1, c0, c1;
            if (i < DIM / 32 - 1) {
                int kn = k0 + 32;
                if (tokr >= 0) {
                    x0 = *(const float4*)(xrow + kn + acol);
                    x1 = *(const float4*)(xrow + kn + acol + 4);
                }
                g0 = *(const float4*)(sGB + kn + acol);
                g1 = *(const float4*)(sGB + kn + acol + 4);
                c0 = *(const float4*)(sGB + DIM + kn + acol);
                c1 = *(const float4*)(sGB + DIM + kn + acol + 4);
            }
            CP_WAIT0();
            __syncthreads();  // W(i) + X(i) visible; MMA(i-1) reads complete
            if (i < DIM / 32 - 1) {
                CP_WT1(k0 + 32, cur ^ 1);
                uint4* xd = cur ? xdst0 : xdst1;
                if (tokr >= 0) {
                    XSTORE(xd, x0, x1, g0, g1, c0, c1);
                } else if (i == 0) {
                    *xd = make_uint4(0u, 0u, 0u, 0u);
                }
            }
            if (do_m) {
                const uint32_t* aw = cur ? aw1 : aw0;
                const uint32_t* ww = (const uint32_t*)(smem + OFF_W + (uint32_t)cur * 20480u);
#pragma unroll
                for (int s = 0; s < 2; s++) {
                    uint32_t afr[2][4];
#pragma unroll
                    for (int m = 0; m < 2; m++) {
                        int bidx = (wm * 32 + m * 16 + g) * LDAW + s * 8 + t4;
                        afr[m][0] = aw[bidx];
                        afr[m][1] = aw[bidx + 8 * LDAW];
                        afr[m][2] = aw[bidx + 4];
                        afr[m][3] = aw[bidx + 8 * LDAW + 4];
                    }
#pragma unroll
                    for (int j = 0; j < 8; j++) {
                        int c = wn * 64 + j * 8 + g;
                        uint32_t bfr[2];
                        bfr[0] = ww[c * LDWW + s * 8 + t4];
                        bfr[1] = ww[c * LDWW + s * 8 + t4 + 4];
                        mma_f16(acc1[0][j], afr[0], bfr);
                        mma_f16(acc1[1][j], afr[1], bfr);
                    }
                }
            }
        }
        CP_WT2(0, 0);  // W2 chunk0 prefetch (W buf0 last read long done)

        // ---- epilogue1: acc1 + b1, ReLU, -> sH1 (half2 words) ----
        if (do_m) {
#pragma unroll
            for (int m = 0; m < 2; m++) {
                int r0 = wm * 32 + m * 16 + g;
#pragma unroll
                for (int j = 0; j < 8; j++) {
                    int c = wn * 64 + j * 8 + 2 * t4;
                    float bx = sB1[c], by = sB1[c + 1];
                    sH1w[r0 * LDH1W + (c >> 1)] =
                        h2u(__floats2half2_rn(fmaxf(acc1[m][j][0] + bx, 0.f),
                                              fmaxf(acc1[m][j][1] + by, 0.f)));
                    sH1w[(r0 + 8) * LDH1W + (c >> 1)] =
                        h2u(__floats2half2_rn(fmaxf(acc1[m][j][2] + bx, 0.f),
                                              fmaxf(acc1[m][j][3] + by, 0.f)));
                }
            }
        }

        // ===================== GEMM2: [128,256] x [256,128], fp16 =====================
        float acc2[2][4][4];
#pragma unroll
        for (int i = 0; i < 2; i++)
#pragma unroll
            for (int j = 0; j < 4; j++)
#pragma unroll
                for (int q = 0; q < 4; q++) acc2[i][j][q] = 0.f;

        for (int i = 0; i < NH / 32; i++) {
            const int cur = i & 1;
            CP_WAIT0();
            __syncthreads();  // W2(i) + (i==0) all H1 stores visible
            if (i < NH / 32 - 1) CP_WT2(i * 32 + 32, cur ^ 1);
            if (do_m) {
                const uint32_t* ww = (const uint32_t*)(smem + OFF_W + (uint32_t)cur * 20480u);
#pragma unroll
                for (int s = 0; s < 2; s++) {
                    uint32_t afr[2][4];
#pragma unroll
                    for (int m = 0; m < 2; m++) {
                        int bidx = (wm * 32 + m * 16 + g) * LDH1W + i * 16 + s * 8 + t4;
                        afr[m][0] = sH1w[bidx];
                        afr[m][1] = sH1w[bidx + 8 * LDH1W];
                        afr[m][2] = sH1w[bidx + 4];
                        afr[m][3] = sH1w[bidx + 8 * LDH1W + 4];
                    }
#pragma unroll
                    for (int j = 0; j < 4; j++) {
                        int c = wn * 32 + j * 8 + g;
                        uint32_t bfr[2];
                        bfr[0] = ww[c * LDWW + s * 8 + t4];
                        bfr[1] = ww[c * LDWW + s * 8 + t4 + 4];
                        mma_f16(acc2[0][j], afr[0], bfr);
                        mma_f16(acc2[1][j], afr[1], bfr);
                    }
                }
            }
        }
        __syncthreads();  // all H1 reads done; H2 (f32) aliases H1

        // ---- epilogue2: acc2 + b2, ReLU, -> sH2 f32 ----
        if (do_m) {
#pragma unroll
            for (int m = 0; m < 2; m++) {
                int r0 = wm * 32 + m * 16 + g;
#pragma unroll
                for (int j = 0; j < 4; j++) {
                    int c = wn * 32 + j * 8 + 2 * t4;
                    float bx = sB2[c], by = sB2[c + 1];
                    *(float2*)&sH2[r0 * LDH2F + c] =
                        make_float2(fmaxf(acc2[m][j][0] + bx, 0.f), fmaxf(acc2[m][j][1] + by, 0.f));
                    *(float2*)&sH2[(r0 + 8) * LDH2F + c] =
                        make_float2(fmaxf(acc2[m][j][2] + bx, 0.f), fmaxf(acc2[m][j][3] + by, 0.f));
                }
            }
        }
        __syncthreads();

        // ---- GEMM3 + residual epilogue ----
        if (tid < 256) {
            int r = tid >> 1, c = tid & 1;
            if (r < rows) {
                int gt = sTok[r];
                if (gt >= 0) {
                    const float4* h4 = (const float4*)&sH2[r * LDH2F];
                    const float4* w4 = (const float4*)&sW3T[c * 128];
                    float s = 0.f;
#pragma unroll
                    for (int k = 0; k < 32; k++) {
                        float4 a = h4[k], b = w4[k];
                        s += a.x * b.x + a.y * b.y + a.z * b.z + a.w * b.w;
                    }
                    float o = 0.7f * (s + b3[(size_t)e * NO + c]) +
                              0.3f * base[(size_t)gt * NO + c];
                    out[(size_t)gt * NO + c] = o;
                }
            }
        }
        __syncthreads();  // protect smem reuse before next stolen tile
    }
}

// ---------------- launcher ----------------
extern "C" void kernel_launch(void* const* d_in, const int* in_sizes, int n_in,
                              void* d_out, int out_size) {
    const float* hidden = (const float*)d_in[0];
    const float* base = (const float*)d_in[1];
    const void* props = d_in[2];
    const float* mask = (const float*)d_in[3];
    const float* ln_g = (const float*)d_in[4];
    const float* ln_b = (const float*)d_in[5];
    const float* W1 = (const float*)d_in[6];
    const float* b1 = (const float*)d_in[7];
    const float* W2 = (const float*)d_in[8];
    const float* b2 = (const float*)d_in[9];
    const float* W3 = (const float*)d_in[10];
    const float* b3 = (const float*)d_in[11];
    float* out = (float*)d_out;

    cudaFuncSetAttribute(k_main, cudaFuncAttributeMaxDynamicSharedMemorySize, SMEM_BYTES);

    k_reset<<<1, 64>>>((const unsigned*)props);
    k_cvt1<<<dim3(DIM / 32, NH / 32, NE), dim3(32, 8)>>>(W1);
    k_cvt2<<<dim3(NH / 32, NH2 / 32, NE), dim3(32, 8)>>>(W2);
    k_stats<<<N_TOK / 8, 256>>>(hidden, props, mask, out);
    k_plan<<<1, 32>>>();
    k_scatter<<<N_TOK / 512, 512>>>(props, mask);
    k_main<<<152, 512, SMEM_BYTES>>>(hidden, base, ln_g, ln_b,
                                     b1, b2, W3, b3, out);
}

// round 10
// speedup vs baseline: 1.1825x; 1.0269x over previous
#include <cuda_runtime.h>
#include <cuda_fp16.h>
#include <cstdint>

#define N_TOK 32768
#define DIM 768
#define NE 64
#define NH 256
#define NH2 128
#define NO 2

// ---------------- scratch (no allocations allowed) ----------------
__device__ int g_hist[NE];
__device__ int g_off[NE + 1];
__device__ int g_cur[NE];
__device__ int g_tokidx[N_TOK];
__device__ int g_ntiles;
__device__ int g_next;
__device__ int g_p64;
#define MAXT 320
__device__ int g_tile_head[MAXT];
__device__ int g_tile_start[MAXT];
__device__ int g_tile_rows[MAXT];
// fp16 normalized activations + folded weights
__device__ __half g_Xh[(size_t)N_TOK * DIM];           // xhat, fp16
__device__ __half g_W1h[(size_t)NE * NH * DIM];        // (diag(gamma)*W1)^T per head
__device__ __half g_W2h[(size_t)NE * NH2 * NH];        // W2^T per head
__device__ float g_b1p[NE * NH];                       // beta @ W1 (accumulated)
__device__ __half g_zero[64];                          // zero row source for padding

// ---------------- helpers ----------------
__device__ __forceinline__ void mma_f16(float* d, const uint32_t* a, const uint32_t* b) {
    asm volatile(
        "mma.sync.aligned.m16n8k16.row.col.f32.f16.f16.f32 "
        "{%0,%1,%2,%3}, {%4,%5,%6,%7}, {%8,%9}, {%0,%1,%2,%3};\n"
        : "+f"(d[0]), "+f"(d[1]), "+f"(d[2]), "+f"(d[3])
        : "r"(a[0]), "r"(a[1]), "r"(a[2]), "r"(a[3]), "r"(b[0]), "r"(b[1]));
}

__device__ __forceinline__ void cp16(uint32_t dst_smem, const void* src) {
    asm volatile("cp.async.cg.shared.global [%0], [%1], 16;\n" ::"r"(dst_smem), "l"(src));
}
#define CP_COMMIT() asm volatile("cp.async.commit_group;\n" ::: "memory")
#define CP_WAIT0() asm volatile("cp.async.wait_group 0;\n" ::: "memory")

__device__ __forceinline__ int get_prop(const void* props, int t, int p64) {
    int v;
    if (p64) v = (int)((const long long*)props)[t];
    else     v = ((const int*)props)[t];
    return v & (NE - 1);
}

__device__ __forceinline__ uint32_t h2u(__half2 h) {
    uint32_t u;
    *(__half2*)&u = h;
    return u;
}

// ---------------- kernel 0: reset + dtype detection + b1p zero ----------------
__global__ void k_reset(const unsigned* __restrict__ pw) {
    int gidx = blockIdx.x * 512 + threadIdx.x;
    if (gidx < NE * NH) g_b1p[gidx] = 0.f;
    if (blockIdx.x == 0) {
        if (threadIdx.x < NE) g_hist[threadIdx.x] = 0;
        if (threadIdx.x >= 64 && threadIdx.x < 96)
            ((uint32_t*)g_zero)[threadIdx.x - 64] = 0u;
        if (threadIdx.x < 32) {
            int odd_nonzero = 0;
#pragma unroll
            for (int i = 0; i < 4; i++)
                if (pw[2 * (threadIdx.x + 32 * i) + 1] != 0u) odd_nonzero = 1;
            unsigned b = __ballot_sync(0xFFFFFFFFu, odd_nonzero);
            if (threadIdx.x == 0) g_p64 = (b == 0u) ? 1 : 0;
        }
    }
}

// ---------------- cvt1: W1 [e][k][n] f32 -> g_W1h [e][n][k] half * gamma, + beta@W1 ----------------
__global__ void k_cvt1(const float* __restrict__ W1,
                       const float* __restrict__ ln_g,
                       const float* __restrict__ ln_b) {
    __shared__ float s[32][33];
    __shared__ float lg[32], lb[32];
    int k0 = blockIdx.x * 32, n0 = blockIdx.y * 32, e = blockIdx.z;
    const float* src = W1 + (size_t)e * DIM * NH;
#pragma unroll
    for (int d = 0; d < 4; d++)
        s[threadIdx.y + 8 * d][threadIdx.x] =
            src[(size_t)(k0 + threadIdx.y + 8 * d) * NH + n0 + threadIdx.x];
    if (threadIdx.y == 0) {
        lg[threadIdx.x] = ln_g[(size_t)e * DIM + k0 + threadIdx.x];
        lb[threadIdx.x] = ln_b[(size_t)e * DIM + k0 + threadIdx.x];
    }
    __syncthreads();
    if (threadIdx.x < 16) {
#pragma unroll
        for (int d = 0; d < 4; d++) {
            int n = n0 + threadIdx.y + 8 * d;
            __half2 h = __floats2half2_rn(
                s[2 * threadIdx.x][threadIdx.y + 8 * d] * lg[2 * threadIdx.x],
                s[2 * threadIdx.x + 1][threadIdx.y + 8 * d] * lg[2 * threadIdx.x + 1]);
            ((__half2*)(g_W1h + (size_t)e * NH * DIM + (size_t)n * DIM + k0))[threadIdx.x] = h;
        }
    }
    if (threadIdx.y == 1) {
        float sum = 0.f;
#pragma unroll
        for (int kk = 0; kk < 32; kk++) sum += lb[kk] * s[kk][threadIdx.x];
        atomicAdd(&g_b1p[e * NH + n0 + threadIdx.x], sum);
    }
}

// ---------------- cvt2: W2 [e][k][n] f32 -> g_W2h [e][n][k] half ----------------
__global__ void k_cvt2(const float* __restrict__ W2) {
    __shared__ float s[32][33];
    int k0 = blockIdx.x * 32, n0 = blockIdx.y * 32, e = blockIdx.z;
    const float* src = W2 + (size_t)e * NH * NH2;
#pragma unroll
    for (int d = 0; d < 4; d++)
        s[threadIdx.y + 8 * d][threadIdx.x] =
            src[(size_t)(k0 + threadIdx.y + 8 * d) * NH2 + n0 + threadIdx.x];
    __syncthreads();
    if (threadIdx.x < 16) {
#pragma unroll
        for (int d = 0; d < 4; d++) {
            int n = n0 + threadIdx.y + 8 * d;
            __half2 h = __floats2half2_rn(s[2 * threadIdx.x][threadIdx.y + 8 * d],
                                          s[2 * threadIdx.x + 1][threadIdx.y + 8 * d]);
            ((__half2*)(g_W2h + (size_t)e * NH2 * NH + (size_t)n * NH + k0))[threadIdx.x] = h;
        }
    }
}

// ---------------- kernel 1: LN -> xhat fp16 + histogram + masked-output zero ----------------
__global__ void k_stats(const float* __restrict__ hidden,
                        const void* __restrict__ props,
                        const float* __restrict__ mask,
                        float* __restrict__ out) {
    int token = blockIdx.x * 8 + (threadIdx.x >> 5);
    int lane = threadIdx.x & 31;
    const float4* xr = (const float4*)(hidden + (size_t)token * DIM);
    float4 v[6];
    float s = 0.f, q = 0.f;
#pragma unroll
    for (int i = 0; i < 6; i++) {
        v[i] = xr[lane + 32 * i];
        s += v[i].x + v[i].y + v[i].z + v[i].w;
        q += v[i].x * v[i].x + v[i].y * v[i].y + v[i].z * v[i].z + v[i].w * v[i].w;
    }
#pragma unroll
    for (int o = 16; o > 0; o >>= 1) {
        s += __shfl_xor_sync(0xFFFFFFFFu, s, o);
        q += __shfl_xor_sync(0xFFFFFFFFu, q, o);
    }
    float mu = s * (1.f / DIM);
    float var = q * (1.f / DIM) - mu * mu;
    float rs = rsqrtf(var + 1e-5f);
    uint2* xd = (uint2*)(g_Xh + (size_t)token * DIM);
#pragma unroll
    for (int i = 0; i < 6; i++) {
        uint2 u;
        u.x = h2u(__floats2half2_rn((v[i].x - mu) * rs, (v[i].y - mu) * rs));
        u.y = h2u(__floats2half2_rn((v[i].z - mu) * rs, (v[i].w - mu) * rs));
        xd[lane + 32 * i] = u;
    }
    if (lane == 0) {
        float m = mask[token];
        if (m > 0.f) {
            atomicAdd(&g_hist[get_prop(props, token, g_p64)], 1);
        } else {
            out[token * 2 + 0] = 0.f;
            out[token * 2 + 1] = 0.f;
        }
    }
}

// ---------------- kernel 2: scan + tile plan ----------------
__global__ void k_plan() {
    if (threadIdx.x == 0) {
        int off = 0, nt = 0;
        for (int e = 0; e < NE; e++) {
            g_off[e] = off;
            int c = g_hist[e];
            for (int s = 0; s < c && nt < MAXT; s += 128) {
                g_tile_head[nt] = e;
                g_tile_start[nt] = off + s;
                g_tile_rows[nt] = min(128, c - s);
                nt++;
            }
            g_cur[e] = 0;
            off += c;
        }
        g_off[NE] = off;
        g_ntiles = nt;
        g_next = 0;
    }
}

// ---------------- kernel 3: scatter ----------------
__global__ void k_scatter(const void* __restrict__ props,
                          const float* __restrict__ mask) {
    __shared__ int h[NE], bs[NE];
    int tid = threadIdx.x;
    int t = blockIdx.x * 512 + tid;
    if (tid < NE) h[tid] = 0;
    __syncthreads();
    int p = -1, loc = 0;
    if (mask[t] > 0.f) {
        p = get_prop(props, t, g_p64);
        loc = atomicAdd(&h[p], 1);
    }
    __syncthreads();
    if (tid < NE && h[tid] > 0) bs[tid] = atomicAdd(&g_cur[tid], h[tid]);
    __syncthreads();
    if (p >= 0) {
        int dst = g_off[p] + bs[p] + loc;
        if (dst >= 0 && dst < N_TOK) g_tokidx[dst] = t;
    }
}

// ---------------- kernel 4: fp16 mma.sync grouped adapter (persistent CTAs) ----------------
#define LDAW 20    // A tile [128 rows][16 words + pad4]
#define LDWW 20    // W tile [n rows][16 words + pad4]
#define LDH1W 132  // H1 [128][128 words + pad4]
#define LDH2F 132  // H2 f32 [128][128 + pad4]

// smem byte offsets
#define OFF_A0 0u          // 10240
#define OFF_A1 10240u      // 10240
#define OFF_W 20480u       // 2 x 20480
#define OFF_H1 61440u      // 67584 (half words; f32 H2 aliases after GEMM2)
#define OFF_H2 61440u
#define OFF_B1 129024u     // 1024
#define OFF_B2 130048u     // 512
#define OFF_W3T 130560u    // 1024
#define OFF_TOK 131584u    // 512
#define SMEM_BYTES 132096u

__global__ __launch_bounds__(512) void k_main(
    const float* __restrict__ base,
    const float* __restrict__ b1, const float* __restrict__ b2,
    const float* __restrict__ W3, const float* __restrict__ b3,
    float* __restrict__ out)
{
    extern __shared__ char smem[];
    const uint32_t sb = (uint32_t)__cvta_generic_to_shared(smem);
    float* sB1 = (float*)(smem + OFF_B1);
    float* sB2 = (float*)(smem + OFF_B2);
    float* sW3T = (float*)(smem + OFF_W3T);
    int* sTok = (int*)(smem + OFF_TOK);
    uint32_t* sH1w = (uint32_t*)(smem + OFF_H1);
    float* sH2 = (float*)(smem + OFF_H2);
    __shared__ int s_tile;

    const int tid = threadIdx.x;
    const int wid = tid >> 5;
    const int lane = tid & 31;
    const int g = lane >> 2;
    const int t4 = lane & 3;
    const int arow = tid >> 2;        // X cp row: 4 threads/row
    const int akc = tid & 3;          // 16B chunk within 64B row-chunk
    const int wm = wid >> 2;
    const int wn = wid & 3;

#define CP_XW1(k0, buf)                                                        \
    {                                                                          \
        const __half* xsrc = (tokr >= 0) ? g_Xh + (size_t)tokr * DIM + (k0) + akc * 8 \
                                         : g_zero + akc * 8;                   \
        cp16(sb + OFF_A0 + (uint32_t)(buf)*10240u + (uint32_t)(arow * 80 + akc * 16), xsrc); \
        const __half* src0 = g_W1h + (size_t)e * NH * DIM + (k0);              \
        _Pragma("unroll") for (int ii = 0; ii < 2; ii++) {                     \
            int idx = tid + 512 * ii;                                          \
            int n = idx >> 2, kc = idx & 3;                                    \
            cp16(sb + OFF_W + (uint32_t)(buf)*20480u + (uint32_t)(n * 80 + kc * 16), \
                 src0 + (size_t)n * DIM + kc * 8);                             \
        }                                                                      \
        CP_COMMIT();                                                           \
    }
#define CP_WT2(k0, buf)                                                        \
    {                                                                          \
        const __half* src0 = g_W2h + (size_t)e * NH2 * NH + (k0);              \
        {                                                                      \
            int n = tid >> 2, kc = tid & 3;                                    \
            cp16(sb + OFF_W + (uint32_t)(buf)*20480u + (uint32_t)(n * 80 + kc * 16), \
                 src0 + (size_t)n * NH + kc * 8);                              \
        }                                                                      \
        CP_COMMIT();                                                           \
    }

    for (;;) {
        if (tid == 0) s_tile = atomicAdd(&g_next, 1);
        __syncthreads();
        const int tile = s_tile;
        if (tile >= g_ntiles) break;

        const int e = g_tile_head[tile] & (NE - 1);
        const int seg = g_tile_start[tile];
        const int rows = g_tile_rows[tile];
        const bool do_m = (wm * 32) < rows;

        // ---- prologue ----
        if (tid < 128) {
            int tok = -1;
            if (tid < rows) {
                tok = g_tokidx[seg + tid];
                if (tok < 0 || tok >= N_TOK) tok = -1;
            }
            sTok[tid] = tok;
        }
        if (tid >= 192 && tid < 256) {
            int i4 = tid - 192;
            float4 a = ((const float4*)(b1 + (size_t)e * NH))[i4];
            float4 b = ((const float4*)(g_b1p + (size_t)e * NH))[i4];
            ((float4*)sB1)[i4] = make_float4(a.x + b.x, a.y + b.y, a.z + b.z, a.w + b.w);
        }
        if (tid >= 256 && tid < 288)
            ((float4*)sB2)[tid - 256] = ((const float4*)(b2 + (size_t)e * NH2))[tid - 256];
        if (tid >= 288 && tid < 416) {
            int k = tid - 288;
            const float* w3e = W3 + (size_t)e * (NH2 * NO);
            sW3T[k] = w3e[k * 2 + 0];
            sW3T[128 + k] = w3e[k * 2 + 1];
        }
        __syncthreads();
        const int tokr = sTok[arow];
        CP_XW1(0, 0);

        // ===================== GEMM1: [128,768] x [768,256], fp16 =====================
        float acc1[2][8][4];
#pragma unroll
        for (int i = 0; i < 2; i++)
#pragma unroll
            for (int j = 0; j < 8; j++)
#pragma unroll
                for (int q = 0; q < 4; q++) acc1[i][j][q] = 0.f;

        const uint32_t* aw0 = (const uint32_t*)(smem + OFF_A0);
        const uint32_t* aw1 = (const uint32_t*)(smem + OFF_A1);

        for (int i = 0; i < DIM / 32; i++) {
            const int cur = i & 1;
            CP_WAIT0();
            __syncthreads();  // X(i)+W(i) visible; MMA(i-1) reads complete
            if (i < DIM / 32 - 1) CP_XW1(i * 32 + 32, cur ^ 1);
            if (do_m) {
                const uint32_t* aw = cur ? aw1 : aw0;
                const uint32_t* ww = (const uint32_t*)(smem + OFF_W + (uint32_t)cur * 20480u);
#pragma unroll
                for (int s = 0; s < 2; s++) {
                    uint32_t afr[2][4];
#pragma unroll
                    for (int m = 0; m < 2; m++) {
                        int bidx = (wm * 32 + m * 16 + g) * LDAW + s * 8 + t4;
                        afr[m][0] = aw[bidx];
                        afr[m][1] = aw[bidx + 8 * LDAW];
                        afr[m][2] = aw[bidx + 4];
                        afr[m][3] = aw[bidx + 8 * LDAW + 4];
                    }
#pragma unroll
                    for (int j = 0; j < 8; j++) {
                        int c = wn * 64 + j * 8 + g;
                        uint32_t bfr[2];
                        bfr[0] = ww[c * LDWW + s * 8 + t4];
                        bfr[1] = ww[c * LDWW + s * 8 + t4 + 4];
                        mma_f16(acc1[0][j], afr[0], bfr);
                        mma_f16(acc1[1][j], afr[1], bfr);
                    }
                }
            }
        }
        CP_WT2(0, 0);  // W2 chunk0 prefetch

        // ---- epilogue1: acc1 + b1', ReLU -> sH1 (half2 words) ----
        if (do_m) {
#pragma unroll
            for (int m = 0; m < 2; m++) {
                int r0 = wm * 32 + m * 16 + g;
#pragma unroll
                for (int j = 0; j < 8; j++) {
                    int c = wn * 64 + j * 8 + 2 * t4;
                    float bx = sB1[c], by = sB1[c + 1];
                    sH1w[r0 * LDH1W + (c >> 1)] =
                        h2u(__floats2half2_rn(fmaxf(acc1[m][j][0] + bx, 0.f),
                                              fmaxf(acc1[m][j][1] + by, 0.f)));
                    sH1w[(r0 + 8) * LDH1W + (c >> 1)] =
                        h2u(__floats2half2_rn(fmaxf(acc1[m][j][2] + bx, 0.f),
                                              fmaxf(acc1[m][j][3] + by, 0.f)));
                }
            }
        }

        // ===================== GEMM2: [128,256] x [256,128], fp16 =====================
        float acc2[2][4][4];
#pragma unroll
        for (int i = 0; i < 2; i++)
#pragma unroll
            for (int j = 0; j < 4; j++)
#pragma unroll
                for (int q = 0; q < 4; q++) acc2[i][j][q] = 0.f;

        for (int i = 0; i < NH / 32; i++) {
            const int cur = i & 1;
            CP_WAIT0();
            __syncthreads();  // W2(i) + (i==0) all H1 stores visible
            if (i < NH / 32 - 1) CP_WT2(i * 32 + 32, cur ^ 1);
            if (do_m) {
                const uint32_t* ww = (const uint32_t*)(smem + OFF_W + (uint32_t)cur * 20480u);
#pragma unroll
                for (int s = 0; s < 2; s++) {
                    uint32_t afr[2][4];
#pragma unroll
                    for (int m = 0; m < 2; m++) {
                        int bidx = (wm * 32 + m * 16 + g) * LDH1W + i * 16 + s * 8 + t4;
                        afr[m][0] = sH1w[bidx];
                        afr[m][1] = sH1w[bidx + 8 * LDH1W];
                        afr[m][2] = sH1w[bidx + 4];
                        afr[m][3] = sH1w[bidx + 8 * LDH1W + 4];
                    }
#pragma unroll
                    for (int j = 0; j < 4; j++) {
                        int c = wn * 32 + j * 8 + g;
                        uint32_t bfr[2];
                        bfr[0] = ww[c * LDWW + s * 8 + t4];
                        bfr[1] = ww[c * LDWW + s * 8 + t4 + 4];
                        mma_f16(acc2[0][j], afr[0], bfr);
                        mma_f16(acc2[1][j], afr[1], bfr);
                    }
                }
            }
        }
        __syncthreads();  // all H1 reads done; H2 (f32) aliases H1

        // ---- epilogue2: acc2 + b2, ReLU -> sH2 f32 ----
        if (do_m) {
#pragma unroll
            for (int m = 0; m < 2; m++) {
                int r0 = wm * 32 + m * 16 + g;
#pragma unroll
                for (int j = 0; j < 4; j++) {
                    int c = wn * 32 + j * 8 + 2 * t4;
                    float bx = sB2[c], by = sB2[c + 1];
                    *(float2*)&sH2[r0 * LDH2F + c] =
                        make_float2(fmaxf(acc2[m][j][0] + bx, 0.f), fmaxf(acc2[m][j][1] + by, 0.f));
                    *(float2*)&sH2[(r0 + 8) * LDH2F + c] =
                        make_float2(fmaxf(acc2[m][j][2] + bx, 0.f), fmaxf(acc2[m][j][3] + by, 0.f));
                }
            }
        }
        __syncthreads();

        // ---- GEMM3 + residual epilogue ----
        if (tid < 256) {
            int r = tid >> 1, c = tid & 1;
            if (r < rows) {
                int gt = sTok[r];
                if (gt >= 0) {
                    const float4* h4 = (const float4*)&sH2[r * LDH2F];
                    const float4* w4 = (const float4*)&sW3T[c * 128];
                    float s = 0.f;
#pragma unroll
                    for (int k = 0; k < 32; k++) {
                        float4 a = h4[k], b = w4[k];
                        s += a.x * b.x + a.y * b.y + a.z * b.z + a.w * b.w;
                    }
                    float o = 0.7f * (s + b3[(size_t)e * NO + c]) +
                              0.3f * base[(size_t)gt * NO + c];
                    out[(size_t)gt * NO + c] = o;
                }
            }
        }
        __syncthreads();  // protect smem reuse before next stolen tile
    }
}

// ---------------- launcher ----------------
extern "C" void kernel_launch(void* const* d_in, const int* in_sizes, int n_in,
                              void* d_out, int out_size) {
    const float* hidden = (const float*)d_in[0];
    const float* base = (const float*)d_in[1];
    const void* props = d_in[2];
    const float* mask = (const float*)d_in[3];
    const float* ln_g = (const float*)d_in[4];
    const float* ln_b = (const float*)d_in[5];
    const float* W1 = (const float*)d_in[6];
    const float* b1 = (const float*)d_in[7];
    const float* W2 = (const float*)d_in[8];
    const float* b2 = (const float*)d_in[9];
    const float* W3 = (const float*)d_in[10];
    const float* b3 = (const float*)d_in[11];
    float* out = (float*)d_out;

    cudaFuncSetAttribute(k_main, cudaFuncAttributeMaxDynamicSharedMemorySize, SMEM_BYTES);

    k_reset<<<32, 512>>>((const unsigned*)props);
    k_cvt1<<<dim3(DIM / 32, NH / 32, NE), dim3(32, 8)>>>(W1, ln_g, ln_b);
    k_cvt2<<<dim3(NH / 32, NH2 / 32, NE), dim3(32, 8)>>>(W2);
    k_stats<<<N_TOK / 8, 256>>>(hidden, props, mask, out);
    k_plan<<<1, 32>>>();
    k_scatter<<<N_TOK / 512, 512>>>(props, mask);
    k_main<<<152, 512, SMEM_BYTES>>>(base, b1, b2, W3, b3, out);
}